// round 6
// baseline (speedup 1.0000x reference)
#include <cuda_runtime.h>
#include <cuda_fp16.h>

#define KK      32
#define HH      4096
#define OUTN    4065
#define EPSV    1e-8f

#define THREADS 512
#define NWARP   16
#define WPC     64           // output cols per warp
#define WC      1024         // output cols per block
#define NSTRIP  4
#define ROWTILES 74
#define ROUT    55
#define DEPTH   3            // prefetch depth (rows)

// smem: img 1024 floats (4KB) + hist 16 warps * 32 slots * 32 lanes * half2 (64KB)
#define SMEM_BYTES (1024 * 4 + NWARP * KK * 32 * 4)

template<int B>
__device__ __forceinline__ void row_step(
    int ir, int r0, int lane, int rows_out,
    int col0, int col1, int col2, int base,
    const float* __restrict__ som, const float* __restrict__ var,
    const float* __restrict__ s_img, __half2* __restrict__ hp,
    float* __restrict__ out,
    float (&sb)[DEPTH][3], float (&vb)[DEPTH][3],
    float& acc0, float& acc1)
{
    const unsigned FULL = 0xffffffffu;
    const int gr = r0 + ir;

    // variance-weighted squared distances for the 3 input cols this lane owns
    const float iv = s_img[((gr & 31) << 5) + lane];
    const float d0 = iv - sb[B][0];
    const float d1 = iv - sb[B][1];
    const float d2 = iv - sb[B][2];
    const float e0 = __fdividef(d0 * d0, vb[B][0] + EPSV);
    const float e1 = __fdividef(d1 * d1, vb[B][1] + EPSV);
    const float e2 = __fdividef(d2 * d2, vb[B][2] + EPSV);

    // refill buffer B with row gr+DEPTH ASAP (row clamped => always a valid address)
    {
        const int pr = min(gr + DEPTH, HH - 1);
        const float* sr = som + (size_t)pr * HH;
        const float* vr = var + (size_t)pr * HH;
        sb[B][0] = __ldg(sr + col0); sb[B][1] = __ldg(sr + col1); sb[B][2] = __ldg(sr + col2);
        vb[B][0] = __ldg(vr + col0); vb[B][1] = __ldg(vr + col1); vb[B][2] = __ldg(vr + col2);
    }

    // --- reduced-shuffle horizontal windows ---
    // T0 = sum(e0), T1 = sum(e1) via xor butterflies (all lanes get total)
    float T0 = e0, T1 = e1;
#pragma unroll
    for (int o = 16; o > 0; o >>= 1) {
        T0 += __shfl_xor_sync(FULL, T0, o);
        T1 += __shfl_xor_sync(FULL, T1, o);
    }
    // inclusive scans of the sliding differences
    float A = e1 - e0;
    float Bv = e2 - e1;
#pragma unroll
    for (int o = 1; o < 32; o <<= 1) {
        float a = __shfl_up_sync(FULL, A, o);
        float b = __shfl_up_sync(FULL, Bv, o);
        if (lane >= o) { A += a; Bv += b; }
    }
    // exclusive versions
    float eA = __shfl_up_sync(FULL, A, 1);
    float eB = __shfl_up_sync(FULL, Bv, 1);
    if (lane == 0) { eA = 0.f; eB = 0.f; }
    const float h0 = T0 + eA;   // window sum @ out col base
    const float h1 = T1 + eB;   // window sum @ out col base+32

    // round h through fp16 FIRST so the add and the later subtract cancel exactly
    const __half2 hh = __floats2half2_rn(h0, h1);
    const float2 hr = __half22float2(hh);

    // vertical sliding window via warp-private 32-row smem ring (no sync needed)
    __half2* hs = hp + ((ir & 31) << 5);
    float o0 = 0.f, o1 = 0.f;
    if (ir >= KK) {
        const float2 old = __half22float2(*hs);
        o0 = old.x; o1 = old.y;
    }
    acc0 += hr.x - o0;
    acc1 += hr.y - o1;
    *hs = hh;

    // emit output row once the 32-row window is full; never write another tile's rows
    if (ir >= KK - 1 && ir < rows_out + KK - 1) {
        const int orow = gr - (KK - 1);
        float* op = out + (size_t)orow * OUTN + base;
        op[0] = acc0;                          // base <= 4063 < OUTN always
        if (base + 32 < OUTN) op[32] = acc1;
    }
}

__global__ __launch_bounds__(THREADS, 2)
void som_boxdist_kernel(const float* __restrict__ img,
                        const float* __restrict__ som,
                        const float* __restrict__ var,
                        float* __restrict__ out)
{
    extern __shared__ __align__(16) float smem[];
    float*   s_img = smem;                       // 1024 floats
    __half2* hist  = (__half2*)(smem + 1024);    // [warp][slot][lane]

    const int t    = threadIdx.x;
    const int lane = t & 31;
    const int w    = t >> 5;
    const int c0   = blockIdx.x * WC;
    const int r0   = blockIdx.y * ROUT;
    const int rows_out = min(ROUT, OUTN - r0);
    const int rows_in  = rows_out + KK - 1;

    const int base = c0 + w * WPC + lane;        // lane's first input/output col
    const int col0 = min(base,      HH - 1);     // clamped (strip 3 right edge)
    const int col1 = min(base + 32, HH - 1);
    const int col2 = min(base + 64, HH - 1);

    for (int i = t; i < KK * KK; i += THREADS) s_img[i] = img[i];

    // depth-3 register prefetch ring
    float sb[DEPTH][3], vb[DEPTH][3];
#pragma unroll
    for (int d = 0; d < DEPTH; ++d) {
        const int pr = min(r0 + d, HH - 1);
        const float* sr = som + (size_t)pr * HH;
        const float* vr = var + (size_t)pr * HH;
        sb[d][0] = __ldg(sr + col0); sb[d][1] = __ldg(sr + col1); sb[d][2] = __ldg(sr + col2);
        vb[d][0] = __ldg(vr + col0); vb[d][1] = __ldg(vr + col1); vb[d][2] = __ldg(vr + col2);
    }

    __syncthreads();    // s_img ready (the ONLY barrier)

    float acc0 = 0.f, acc1 = 0.f;
    __half2* hp = hist + w * (KK * 32) + lane;   // + slot*32

    const int nloop = ((rows_in + DEPTH - 1) / DEPTH) * DEPTH;

    for (int ir = 0; ir < nloop; ir += DEPTH) {
        row_step<0>(ir + 0, r0, lane, rows_out, col0, col1, col2, base,
                    som, var, s_img, hp, out, sb, vb, acc0, acc1);
        row_step<1>(ir + 1, r0, lane, rows_out, col0, col1, col2, base,
                    som, var, s_img, hp, out, sb, vb, acc0, acc1);
        row_step<2>(ir + 2, r0, lane, rows_out, col0, col1, col2, base,
                    som, var, s_img, hp, out, sb, vb, acc0, acc1);
    }
}

extern "C" void kernel_launch(void* const* d_in, const int* in_sizes, int n_in,
                              void* d_out, int out_size)
{
    (void)in_sizes; (void)n_in; (void)out_size;
    const float* img = (const float*)d_in[0];
    const float* som = (const float*)d_in[1];
    const float* var = (const float*)d_in[2];
    float* out = (float*)d_out;

    const size_t shmem = SMEM_BYTES;             // 69,632 B -> 2 blocks/SM
    cudaFuncSetAttribute(som_boxdist_kernel,
                         cudaFuncAttributeMaxDynamicSharedMemorySize, (int)shmem);

    dim3 grid(NSTRIP, ROWTILES);                 // 4 x 74 = 296 blocks = 2/SM
    som_boxdist_kernel<<<grid, THREADS, shmem>>>(img, som, var, out);
}